// round 13
// baseline (speedup 1.0000x reference)
#include <cuda_runtime.h>
#include <cuda_bf16.h>
#include <cstdint>

#define NN 128
#define LL 512
#define HIDDEN 512
#define EMBED 256
#define GCTAS 128
#define TTHR 512

// CTA = (mslice: 32 rows) x (colgrp: 16 h-cols = 64 gate-cols)
// 16 warps = kq(warp>>2) x nq(warp&3); warp M32 x N16; window w: warp computes
// tile 2w+(kq>>1), kk half (kq&1). B frags prefetched across the barrier.
// h publication: per-(mslice,colgrp) release flags; consumers poll exactly the
// producer of the chunk they stage.

#define WSTR 1552
#define SM_WH 0
#define SM_WL 99328
#define SM_A  198656
#define ABUF  8192
#define ASPL  4096
#define SM_TOT 231424        // 198656 + 4*8192

__device__ __nv_bfloat16 g_hh[2][NN * HIDDEN];
__device__ __nv_bfloat16 g_hl[2][NN * HIDDEN];
__device__ __nv_bfloat16 g_xh[LL][NN * EMBED];
__device__ __nv_bfloat16 g_xl[LL][NN * EMBED];
__device__ unsigned g_ecnt;
__device__ volatile unsigned g_egen;
__device__ volatile unsigned g_flag[128];   // [mslice*32 + colgrp] == t+1 when h_t done

__device__ __forceinline__ uint32_t smem_u32(const void* p) {
    uint32_t a;
    asm("{ .reg .u64 t; cvta.to.shared.u64 t, %1; cvt.u32.u64 %0, t; }" : "=r"(a) : "l"(p));
    return a;
}
__device__ __forceinline__ float sigf(float x) {
    return __fdividef(1.0f, 1.0f + __expf(-x));
}
__device__ __forceinline__ float tanhf_fast(float x) {
    return __fdividef(2.0f, 1.0f + __expf(-2.0f * x)) - 1.0f;
}

#define LDSM4(r0, r1, r2, r3, ad)                                                \
    asm volatile("ldmatrix.sync.aligned.m8n8.x4.shared.b16 {%0,%1,%2,%3}, [%4];" \
                 : "=r"(r0), "=r"(r1), "=r"(r2), "=r"(r3) : "r"(ad))

__device__ __forceinline__ void mma16816(float* d, uint32_t a0, uint32_t a1,
                                         uint32_t a2, uint32_t a3, uint32_t b0,
                                         uint32_t b1) {
    asm volatile(
        "mma.sync.aligned.m16n8k16.row.col.f32.bf16.bf16.f32 "
        "{%0,%1,%2,%3},{%4,%5,%6,%7},{%8,%9},{%0,%1,%2,%3};"
        : "+f"(d[0]), "+f"(d[1]), "+f"(d[2]), "+f"(d[3])
        : "r"(a0), "r"(a1), "r"(a2), "r"(a3), "r"(b0), "r"(b1));
}

__device__ __forceinline__ void entrybarrier() {
    __syncthreads();
    if (threadIdx.x == 0) {
        unsigned my = g_egen;
        __threadfence();
        unsigned old = atomicAdd(&g_ecnt, 1u);
        if (old == (GCTAS - 1)) {
            atomicExch(&g_ecnt, 0u);
            __threadfence();
            g_egen = my + 1u;
        } else {
            while (g_egen == my) { __nanosleep(64); }
        }
        __threadfence();
    }
    __syncthreads();
}

// stage a PAIR of k64 tiles (T, T+1) -> bufs T%4, (T+1)%4. One commit group.
__device__ __forceinline__ void stage_pair(int tid, uint32_t su, int T,
                                           const char* ah, const char* al,
                                           int astr, int koff0) {
    const int split = tid >> 8, row = (tid >> 3) & 31, ch = tid & 7;
    const uint32_t off =
        (uint32_t)(split * ASPL + row * 128 + ((ch ^ (row & 7)) << 4));
    const char* s0 = (split ? al : ah) + row * astr + koff0 + ch * 16;
    const char* s1 = s0 + 128;
    uint32_t d0 = su + SM_A + (uint32_t)((T & 3) * ABUF) + off;
    uint32_t d1 = su + SM_A + (uint32_t)(((T + 1) & 3) * ABUF) + off;
    asm volatile("cp.async.cg.shared.global [%0], [%1], 16;" ::"r"(d0), "l"(s0));
    asm volatile("cp.async.cg.shared.global [%0], [%1], 16;" ::"r"(d1), "l"(s1));
    asm volatile("cp.async.commit_group;" ::: "memory");
}

// load B fragments (hi+lo, both kx) for tile T_ into a 16-reg array
#define LOAD_B(dst, T_)                                                             \
    do {                                                                            \
        _Pragma("unroll")                                                           \
        for (int kx = 0; kx < 2; kx++) {                                            \
            const uint32_t kb = (uint32_t)((T_) * 128 + (kk0 + kx) * 32);           \
            LDSM4((dst)[kx * 8 + 0], (dst)[kx * 8 + 1], (dst)[kx * 8 + 2],          \
                  (dst)[kx * 8 + 3], bWh + kb);                                     \
            LDSM4((dst)[kx * 8 + 4], (dst)[kx * 8 + 5], (dst)[kx * 8 + 6],          \
                  (dst)[kx * 8 + 7], bWl + kb);                                     \
        }                                                                           \
    } while (0)

extern __shared__ char smem_raw[];

__global__ void __launch_bounds__(TTHR, 1)
lstm_hmma(const int* __restrict__ X, const float* __restrict__ E,
          const float* __restrict__ Wi, const float* __restrict__ bi,
          const float* __restrict__ Wf, const float* __restrict__ bf,
          const float* __restrict__ Wo, const float* __restrict__ bo,
          const float* __restrict__ Wh, const float* __restrict__ bh,
          float* __restrict__ out) {
    __shared__ int toks[NN];

    const int tid = threadIdx.x;
    const int warp = tid >> 5;
    const int lane = tid & 31;
    const int kq = warp >> 2;
    const int nq = warp & 3;
    const uint32_t su = smem_u32(smem_raw);
    char* dyn = smem_raw;
    float* red = (float*)(smem_raw + SM_A);

    const int mslice = blockIdx.x & 3;
    const int colgrp = blockIdx.x >> 2;
    const int mbase = mslice * 32;
    const int colbase = colgrp * 16;

    if (blockIdx.x == 0 && tid < 128) g_flag[tid] = 0u;

    // ---- weights resident (hi + lo), rows n = hcol_local*4 + gate ----
    for (int n = 0; n < 64; n++) {
        int hc = colbase + (n >> 2), gate = n & 3;
        const float* Wg = (gate == 0) ? Wi : (gate == 1) ? Wf : (gate == 2) ? Wo : Wh;
        for (int j = tid; j < 768; j += TTHR) {
            int k = (j < 256) ? (512 + j) : (j - 256);
            float w = Wg[k * HIDDEN + hc];
            __nv_bfloat16 hi = __float2bfloat16(w);
            *(__nv_bfloat16*)(dyn + SM_WH + n * WSTR + j * 2) = hi;
            *(__nv_bfloat16*)(dyn + SM_WL + n * WSTR + j * 2) =
                __float2bfloat16(w - __bfloat162float(hi));
        }
    }

    // ---- embeddings (hi/lo), 4 timesteps per CTA, layout [t][m][e] ----
    for (int tt = 0; tt < 4; tt++) {
        int t = blockIdx.x * 4 + tt;
        __syncthreads();
        if (tid < NN) toks[tid] = X[tid * LL + t];
        __syncthreads();
        __nv_bfloat16* dh = g_xh[t];
        __nv_bfloat16* dl = g_xl[t];
        for (int i = tid; i < NN * EMBED; i += TTHR) {
            float v = E[(size_t)toks[i >> 8] * EMBED + (i & 255)];
            __nv_bfloat16 hi = __float2bfloat16(v);
            dh[i] = hi;
            dl[i] = __float2bfloat16(v - __bfloat162float(hi));
        }
    }
    if (tid < 256) {
        ((unsigned*)g_hh[0])[blockIdx.x * 256 + tid] = 0u;
        ((unsigned*)g_hl[0])[blockIdx.x * 256 + tid] = 0u;
    }

    // ---- A fragment addressing (swizzled; verified mapping) ----
    const int row16 = lane & 15, c0 = lane >> 4, r7 = row16 & 7;
    const uint32_t arow = (uint32_t)(row16 * 128);
    // ---- B fragment addressing (padded resident W) ----
    const uint32_t bW_off =
        (uint32_t)((nq * 16 + (lane >> 4) * 8 + (lane & 7)) * WSTR +
                   ((lane >> 3) & 1) * 16);
    const uint32_t bWh = su + SM_WH + bW_off;
    const uint32_t bWl = su + SM_WL + bW_off;

    const int tsel = kq >> 1;        // which tile of the pair
    const int kk0 = (kq & 1) * 2;    // which kk half

    // ---- epilogue role: one cell per thread ----
    const int me = tid >> 4;
    const int hce = tid & 15;
    int bidx[4];
    float b4[4];
#pragma unroll
    for (int g = 0; g < 4; g++) {
        int n = hce * 4 + g;
        int nqr = n >> 4, nt = (n >> 3) & 1, nc = n & 7;
        int mt = me >> 4, mr = me & 15;
        int lane_r = (mr & 7) * 4 + (nc >> 1);
        int d = (mr >> 3) * 2 + (nc & 1);
        int f = mt * 8 + nt * 4 + d;
        bidx[g] = nqr * 512 + f * 32 + lane_r;
    }
    b4[0] = bi[colbase + hce];
    b4[1] = bf[colbase + hce];
    b4[2] = bo[colbase + hce];
    b4[3] = bh[colbase + hce];
    float cs = 0.0f;

    // poll bookkeeping for staging threads
    const int pch = tid & 7;                  // chunk index in stage_pair
    const int fbase = mslice * 32 + (pch >> 1);

    entrybarrier();

    // prologue: stage step-0 x pairs 0,1 and preload window-0 B frags
    stage_pair(tid, su, 0, (const char*)g_xh[0] + mbase * 512,
               (const char*)g_xl[0] + mbase * 512, 512, 0);
    stage_pair(tid, su, 2, (const char*)g_xh[0] + mbase * 512,
               (const char*)g_xl[0] + mbase * 512, 512, 256);

    uint32_t Bc[16], Bn[16];
    LOAD_B(Bc, tsel);

    for (int t = 0; t < LL; t++) {
        float D0[2][2][4], D1a[2][2][4], D1b[2][2][4];
#pragma unroll
        for (int a = 0; a < 2; a++)
#pragma unroll
            for (int b = 0; b < 2; b++)
#pragma unroll
                for (int d = 0; d < 4; d++) {
                    D0[a][b][d] = 0.0f;
                    D1a[a][b][d] = 0.0f;
                    D1b[a][b][d] = 0.0f;
                }

#pragma unroll 1
        for (int w = 0; w < 6; w++) {
            // prefetch next window's B frags (resident W — safe before barriers)
            const int nextT = (w < 5) ? (2 * (w + 1) + tsel) : tsel;
            LOAD_B(Bn, nextT);

            if (w == 5)
                asm volatile("cp.async.wait_group 0;" ::: "memory");
            else
                asm volatile("cp.async.wait_group 1;" ::: "memory");
            __syncthreads();

            // ---- compute own (tile, kk-half) of pair w using prefetched Bc ----
            {
                const int myT = 2 * w + tsel;
                const uint32_t Ab = su + SM_A + (uint32_t)((myT & 3) * ABUF) + arow;
#pragma unroll
                for (int kx = 0; kx < 2; kx++) {
                    const int kk = kk0 + kx;
                    const uint32_t sw = (uint32_t)(((kk * 2 + c0) ^ r7) << 4);
                    uint32_t ab = Ab + sw;
                    uint32_t h00, h01, h02, h03, h10, h11, h12, h13;
                    uint32_t l00, l01, l02, l03, l10, l11, l12, l13;
                    LDSM4(h00, h01, h02, h03, ab);
                    LDSM4(h10, h11, h12, h13, ab + 2048);
                    LDSM4(l00, l01, l02, l03, ab + ASPL);
                    LDSM4(l10, l11, l12, l13, ab + ASPL + 2048);
                    const uint32_t bh0 = Bc[kx * 8 + 0], bh1 = Bc[kx * 8 + 1];
                    const uint32_t bh2 = Bc[kx * 8 + 2], bh3 = Bc[kx * 8 + 3];
                    const uint32_t bl0 = Bc[kx * 8 + 4], bl1 = Bc[kx * 8 + 5];
                    const uint32_t bl2 = Bc[kx * 8 + 6], bl3 = Bc[kx * 8 + 7];
                    mma16816(D0[0][0], h00, h01, h02, h03, bh0, bh1);
                    mma16816(D0[0][1], h00, h01, h02, h03, bh2, bh3);
                    mma16816(D0[1][0], h10, h11, h12, h13, bh0, bh1);
                    mma16816(D0[1][1], h10, h11, h12, h13, bh2, bh3);
                    mma16816(D1a[0][0], l00, l01, l02, l03, bh0, bh1);
                    mma16816(D1a[0][1], l00, l01, l02, l03, bh2, bh3);
                    mma16816(D1a[1][0], l10, l11, l12, l13, bh0, bh1);
                    mma16816(D1a[1][1], l10, l11, l12, l13, bh2, bh3);
                    mma16816(D1b[0][0], h00, h01, h02, h03, bl0, bl1);
                    mma16816(D1b[0][1], h00, h01, h02, h03, bl2, bl3);
                    mma16816(D1b[1][0], h10, h11, h12, h13, bl0, bl1);
                    mma16816(D1b[1][1], h10, h11, h12, h13, bl2, bl3);
                }
            }

            // ---- stage pair w+2 AFTER compute (ring-4 safe) ----
            if (w < 4) {
                __syncthreads();   // all warps done reading pair w's buffers
                const int T = 2 * w + 4;
                // fine-grained poll: only the producer colgrps of MY chunks
                const int f0 = fbase + 8 * w;
                while (g_flag[f0] < (unsigned)t) { __nanosleep(16); }
                while (g_flag[f0 + 4] < (unsigned)t) { __nanosleep(16); }
                int hp = t & 1;
                stage_pair(tid, su, T, (const char*)g_hh[hp] + mbase * 1024,
                           (const char*)g_hl[hp] + mbase * 1024, 1024,
                           (T - 4) * 128);
            }

            // swap prefetched B into current
#pragma unroll
            for (int i = 0; i < 16; i++) Bc[i] = Bn[i];
        }

        // ---- merge chains ----
        float S[16];
#pragma unroll
        for (int a = 0; a < 2; a++)
#pragma unroll
            for (int b = 0; b < 2; b++)
#pragma unroll
                for (int d = 0; d < 4; d++)
                    S[a * 8 + b * 4 + d] =
                        D0[a][b][d] + D1a[a][b][d] + D1b[a][b][d];

        // ---- single-phase cross-kq reduction over the drained 32KB ring ----
        __syncthreads();
        {
            int base = warp * 512 + lane;
#pragma unroll
            for (int f = 0; f < 16; f++) red[base + f * 32] = S[f];
        }
        __syncthreads();
        float a4[4];
#pragma unroll
        for (int g = 0; g < 4; g++)
            a4[g] = (red[bidx[g]] + red[bidx[g] + 2048]) +
                    (red[bidx[g] + 4096] + red[bidx[g] + 6144]);
        __syncthreads();   // reads done before staging overwrites the ring

        // ---- stage next step's x pairs 0,1 (pure x, no h dependency) ----
        if (t + 1 < LL) {
            stage_pair(tid, su, 0, (const char*)g_xh[t + 1] + mbase * 512,
                       (const char*)g_xl[t + 1] + mbase * 512, 512, 0);
            stage_pair(tid, su, 2, (const char*)g_xh[t + 1] + mbase * 512,
                       (const char*)g_xl[t + 1] + mbase * 512, 512, 256);
        }

        // ---- gates + state update + publish ----
        const int pn = (t & 1) ^ 1;
        {
            float iv = sigf(a4[0] + b4[0]);
            float fv = sigf(a4[1] + b4[1]);
            float ov = sigf(a4[2] + b4[2]);
            float gv = tanhf_fast(a4[3] + b4[3]);
            cs = fv * cs + iv * gv;
            float hv = ov * tanhf_fast(cs);
            int mg = mbase + me, hcg = colbase + hce;
            __nv_bfloat16 hi = __float2bfloat16(hv);
            g_hh[pn][mg * HIDDEN + hcg] = hi;
            g_hl[pn][mg * HIDDEN + hcg] = __float2bfloat16(hv - __bfloat162float(hi));
            if (t == LL - 1) out[mg * HIDDEN + hcg] = hv;
        }

        // ---- release-flag publish: no atomics, no fan-in ----
        __syncthreads();
        if (tid == 0) {
            __threadfence();
            g_flag[mslice * 32 + colgrp] = (unsigned)(t + 1);
        }
    }
}

extern "C" void kernel_launch(void* const* d_in, const int* in_sizes, int n_in,
                              void* d_out, int out_size) {
    const int* X = (const int*)d_in[0];
    const float* E = (const float*)d_in[1];
    const float* Wi = (const float*)d_in[2];
    const float* bi = (const float*)d_in[3];
    const float* Wf = (const float*)d_in[4];
    const float* bf = (const float*)d_in[5];
    const float* Wo = (const float*)d_in[6];
    const float* bo = (const float*)d_in[7];
    const float* Wh = (const float*)d_in[8];
    const float* bh = (const float*)d_in[9];
    float* out = (float*)d_out;

    cudaFuncSetAttribute(lstm_hmma, cudaFuncAttributeMaxDynamicSharedMemorySize,
                         SM_TOT);
    lstm_hmma<<<GCTAS, TTHR, SM_TOT>>>(X, E, Wi, bi, Wf, bf, Wo, bo, Wh, bh, out);
}

// round 14
// speedup vs baseline: 1.5923x; 1.5923x over previous
#include <cuda_runtime.h>
#include <cuda_bf16.h>
#include <cstdint>

#define NN 128
#define LL 512
#define HIDDEN 512
#define EMBED 256
#define GCTAS 128
#define TTHR 512

// CTA = (mslice: 32 rows) x (colgrp: 16 h-cols = 64 gate-cols)
// 16 warps = kq(warp>>2) x nq(warp&3); window w: warp computes tile 2w+(kq>>1),
// kk half (kq&1). B frags prefetched across the barrier (resident W region).
// h publication: per-mslice counter (R12-proven); poll by warp 0 only.

#define WSTR 1552
#define SM_WH 0
#define SM_WL 99328
#define SM_A  198656
#define ABUF  8192
#define ASPL  4096
#define SM_TOT 231424        // 198656 + 4*8192

__device__ __nv_bfloat16 g_hh[2][NN * HIDDEN];
__device__ __nv_bfloat16 g_hl[2][NN * HIDDEN];
__device__ __nv_bfloat16 g_xh[LL][NN * EMBED];
__device__ __nv_bfloat16 g_xl[LL][NN * EMBED];
__device__ unsigned g_ecnt;
__device__ volatile unsigned g_egen;
__device__ unsigned g_cntM[4 * 32];             // per-mslice arrival counters (padded)
__device__ volatile unsigned g_genM[4 * 32];    // per-mslice: == t+1 when h_t done

__device__ __forceinline__ uint32_t smem_u32(const void* p) {
    uint32_t a;
    asm("{ .reg .u64 t; cvta.to.shared.u64 t, %1; cvt.u32.u64 %0, t; }" : "=r"(a) : "l"(p));
    return a;
}
__device__ __forceinline__ float sigf(float x) {
    return __fdividef(1.0f, 1.0f + __expf(-x));
}
__device__ __forceinline__ float tanhf_fast(float x) {
    return __fdividef(2.0f, 1.0f + __expf(-2.0f * x)) - 1.0f;
}

#define LDSM4(r0, r1, r2, r3, ad)                                                \
    asm volatile("ldmatrix.sync.aligned.m8n8.x4.shared.b16 {%0,%1,%2,%3}, [%4];" \
                 : "=r"(r0), "=r"(r1), "=r"(r2), "=r"(r3) : "r"(ad))

__device__ __forceinline__ void mma16816(float* d, uint32_t a0, uint32_t a1,
                                         uint32_t a2, uint32_t a3, uint32_t b0,
                                         uint32_t b1) {
    asm volatile(
        "mma.sync.aligned.m16n8k16.row.col.f32.bf16.bf16.f32 "
        "{%0,%1,%2,%3},{%4,%5,%6,%7},{%8,%9},{%0,%1,%2,%3};"
        : "+f"(d[0]), "+f"(d[1]), "+f"(d[2]), "+f"(d[3])
        : "r"(a0), "r"(a1), "r"(a2), "r"(a3), "r"(b0), "r"(b1));
}

__device__ __forceinline__ void entrybarrier() {
    __syncthreads();
    if (threadIdx.x == 0) {
        unsigned my = g_egen;
        __threadfence();
        unsigned old = atomicAdd(&g_ecnt, 1u);
        if (old == (GCTAS - 1)) {
            atomicExch(&g_ecnt, 0u);
            __threadfence();
            g_egen = my + 1u;
        } else {
            while (g_egen == my) { __nanosleep(64); }
        }
        __threadfence();
    }
    __syncthreads();
}

// stage a PAIR of k64 tiles (T, T+1) -> bufs T%4, (T+1)%4. One commit group.
__device__ __forceinline__ void stage_pair(int tid, uint32_t su, int T,
                                           const char* ah, const char* al,
                                           int astr, int koff0) {
    const int split = tid >> 8, row = (tid >> 3) & 31, ch = tid & 7;
    const uint32_t off =
        (uint32_t)(split * ASPL + row * 128 + ((ch ^ (row & 7)) << 4));
    const char* s0 = (split ? al : ah) + row * astr + koff0 + ch * 16;
    const char* s1 = s0 + 128;
    uint32_t d0 = su + SM_A + (uint32_t)((T & 3) * ABUF) + off;
    uint32_t d1 = su + SM_A + (uint32_t)(((T + 1) & 3) * ABUF) + off;
    asm volatile("cp.async.cg.shared.global [%0], [%1], 16;" ::"r"(d0), "l"(s0));
    asm volatile("cp.async.cg.shared.global [%0], [%1], 16;" ::"r"(d1), "l"(s1));
    asm volatile("cp.async.commit_group;" ::: "memory");
}

// load B fragments (hi+lo, both kx of this warp's kk half) for tile T_
#define LOAD_B(dst, T_)                                                             \
    do {                                                                            \
        _Pragma("unroll")                                                           \
        for (int kx = 0; kx < 2; kx++) {                                            \
            const uint32_t kb = (uint32_t)((T_) * 128 + (kk0 + kx) * 32);           \
            LDSM4((dst)[kx * 8 + 0], (dst)[kx * 8 + 1], (dst)[kx * 8 + 2],          \
                  (dst)[kx * 8 + 3], bWh + kb);                                     \
            LDSM4((dst)[kx * 8 + 4], (dst)[kx * 8 + 5], (dst)[kx * 8 + 6],          \
                  (dst)[kx * 8 + 7], bWl + kb);                                     \
        }                                                                           \
    } while (0)

extern __shared__ char smem_raw[];

__global__ void __launch_bounds__(TTHR, 1)
lstm_hmma(const int* __restrict__ X, const float* __restrict__ E,
          const float* __restrict__ Wi, const float* __restrict__ bi,
          const float* __restrict__ Wf, const float* __restrict__ bf,
          const float* __restrict__ Wo, const float* __restrict__ bo,
          const float* __restrict__ Wh, const float* __restrict__ bh,
          float* __restrict__ out) {
    __shared__ int toks[NN];

    const int tid = threadIdx.x;
    const int warp = tid >> 5;
    const int lane = tid & 31;
    const int kq = warp >> 2;
    const int nq = warp & 3;
    const uint32_t su = smem_u32(smem_raw);
    char* dyn = smem_raw;
    float* red = (float*)(smem_raw + SM_A);

    const int mslice = blockIdx.x & 3;
    const int colgrp = blockIdx.x >> 2;
    const int mbase = mslice * 32;
    const int colbase = colgrp * 16;

    if (blockIdx.x == 0 && tid < 4) {
        g_cntM[tid * 32] = 0u;
        g_genM[tid * 32] = 0u;
    }

    // ---- weights resident (hi + lo), rows n = hcol_local*4 + gate ----
    for (int n = 0; n < 64; n++) {
        int hc = colbase + (n >> 2), gate = n & 3;
        const float* Wg = (gate == 0) ? Wi : (gate == 1) ? Wf : (gate == 2) ? Wo : Wh;
        for (int j = tid; j < 768; j += TTHR) {
            int k = (j < 256) ? (512 + j) : (j - 256);
            float w = Wg[k * HIDDEN + hc];
            __nv_bfloat16 hi = __float2bfloat16(w);
            *(__nv_bfloat16*)(dyn + SM_WH + n * WSTR + j * 2) = hi;
            *(__nv_bfloat16*)(dyn + SM_WL + n * WSTR + j * 2) =
                __float2bfloat16(w - __bfloat162float(hi));
        }
    }

    // ---- embeddings (hi/lo), 4 timesteps per CTA, layout [t][m][e] ----
    for (int tt = 0; tt < 4; tt++) {
        int t = blockIdx.x * 4 + tt;
        __syncthreads();
        if (tid < NN) toks[tid] = X[tid * LL + t];
        __syncthreads();
        __nv_bfloat16* dh = g_xh[t];
        __nv_bfloat16* dl = g_xl[t];
        for (int i = tid; i < NN * EMBED; i += TTHR) {
            float v = E[(size_t)toks[i >> 8] * EMBED + (i & 255)];
            __nv_bfloat16 hi = __float2bfloat16(v);
            dh[i] = hi;
            dl[i] = __float2bfloat16(v - __bfloat162float(hi));
        }
    }
    if (tid < 256) {
        ((unsigned*)g_hh[0])[blockIdx.x * 256 + tid] = 0u;
        ((unsigned*)g_hl[0])[blockIdx.x * 256 + tid] = 0u;
    }

    // ---- A fragment addressing (swizzled; verified mapping) ----
    const int row16 = lane & 15, c0 = lane >> 4, r7 = row16 & 7;
    const uint32_t arow = (uint32_t)(row16 * 128);
    // ---- B fragment addressing (padded resident W) ----
    const uint32_t bW_off =
        (uint32_t)((nq * 16 + (lane >> 4) * 8 + (lane & 7)) * WSTR +
                   ((lane >> 3) & 1) * 16);
    const uint32_t bWh = su + SM_WH + bW_off;
    const uint32_t bWl = su + SM_WL + bW_off;

    const int tsel = kq >> 1;        // which tile of the pair
    const int kk0 = (kq & 1) * 2;    // which kk half

    // ---- epilogue role: one cell per thread ----
    const int me = tid >> 4;
    const int hce = tid & 15;
    int bidx[4];
    float b4[4];
#pragma unroll
    for (int g = 0; g < 4; g++) {
        int n = hce * 4 + g;
        int nqr = n >> 4, nt = (n >> 3) & 1, nc = n & 7;
        int mt = me >> 4, mr = me & 15;
        int lane_r = (mr & 7) * 4 + (nc >> 1);
        int d = (mr >> 3) * 2 + (nc & 1);
        int f = mt * 8 + nt * 4 + d;
        bidx[g] = nqr * 512 + f * 32 + lane_r;
    }
    b4[0] = bi[colbase + hce];
    b4[1] = bf[colbase + hce];
    b4[2] = bo[colbase + hce];
    b4[3] = bh[colbase + hce];
    float cs = 0.0f;

    entrybarrier();

    // prologue: stage step-0 x pairs 0,1 and preload window-0 B frags
    stage_pair(tid, su, 0, (const char*)g_xh[0] + mbase * 512,
               (const char*)g_xl[0] + mbase * 512, 512, 0);
    stage_pair(tid, su, 2, (const char*)g_xh[0] + mbase * 512,
               (const char*)g_xl[0] + mbase * 512, 512, 256);

    uint32_t Bc[16], Bn[16];
    LOAD_B(Bc, tsel);

    for (int t = 0; t < LL; t++) {
        float D0[2][2][4], D1a[2][2][4], D1b[2][2][4];
#pragma unroll
        for (int a = 0; a < 2; a++)
#pragma unroll
            for (int b = 0; b < 2; b++)
#pragma unroll
                for (int d = 0; d < 4; d++) {
                    D0[a][b][d] = 0.0f;
                    D1a[a][b][d] = 0.0f;
                    D1b[a][b][d] = 0.0f;
                }

#pragma unroll 1
        for (int w = 0; w < 6; w++) {
            // prefetch next window's B frags (resident W region; barrier-safe)
            const int nextT = (w < 5) ? (2 * (w + 1) + tsel) : tsel;
            LOAD_B(Bn, nextT);

            if (w == 5)
                asm volatile("cp.async.wait_group 0;" ::: "memory");
            else
                asm volatile("cp.async.wait_group 1;" ::: "memory");
            __syncthreads();

            // ---- compute own (tile, kk-half) of pair w with prefetched Bc ----
            {
                const int myT = 2 * w + tsel;
                const uint32_t Ab = su + SM_A + (uint32_t)((myT & 3) * ABUF) + arow;
#pragma unroll
                for (int kx = 0; kx < 2; kx++) {
                    const int kk = kk0 + kx;
                    const uint32_t sw = (uint32_t)(((kk * 2 + c0) ^ r7) << 4);
                    uint32_t ab = Ab + sw;
                    uint32_t h00, h01, h02, h03, h10, h11, h12, h13;
                    uint32_t l00, l01, l02, l03, l10, l11, l12, l13;
                    LDSM4(h00, h01, h02, h03, ab);
                    LDSM4(h10, h11, h12, h13, ab + 2048);
                    LDSM4(l00, l01, l02, l03, ab + ASPL);
                    LDSM4(l10, l11, l12, l13, ab + ASPL + 2048);
                    const uint32_t bh0 = Bc[kx * 8 + 0], bh1 = Bc[kx * 8 + 1];
                    const uint32_t bh2 = Bc[kx * 8 + 2], bh3 = Bc[kx * 8 + 3];
                    const uint32_t bl0 = Bc[kx * 8 + 4], bl1 = Bc[kx * 8 + 5];
                    const uint32_t bl2 = Bc[kx * 8 + 6], bl3 = Bc[kx * 8 + 7];
                    mma16816(D0[0][0], h00, h01, h02, h03, bh0, bh1);
                    mma16816(D0[0][1], h00, h01, h02, h03, bh2, bh3);
                    mma16816(D0[1][0], h10, h11, h12, h13, bh0, bh1);
                    mma16816(D0[1][1], h10, h11, h12, h13, bh2, bh3);
                    mma16816(D1a[0][0], l00, l01, l02, l03, bh0, bh1);
                    mma16816(D1a[0][1], l00, l01, l02, l03, bh2, bh3);
                    mma16816(D1a[1][0], l10, l11, l12, l13, bh0, bh1);
                    mma16816(D1a[1][1], l10, l11, l12, l13, bh2, bh3);
                    mma16816(D1b[0][0], h00, h01, h02, h03, bl0, bl1);
                    mma16816(D1b[0][1], h00, h01, h02, h03, bl2, bl3);
                    mma16816(D1b[1][0], h10, h11, h12, h13, bl0, bl1);
                    mma16816(D1b[1][1], h10, h11, h12, h13, bl2, bl3);
                }
            }

            // ---- stage pair w+2 AFTER compute (ring-4 safe) ----
            if (w < 4) {
                __syncthreads();   // all warps done reading pair w's buffers
                const int T = 2 * w + 4;
                if (w == 0) {
                    // warp-0-only uniform poll, then barrier
                    if (warp == 0) {
                        while (g_genM[mslice * 32] < (unsigned)t) { __nanosleep(64); }
                    }
                    __syncthreads();
                }
                int hp = t & 1;
                stage_pair(tid, su, T, (const char*)g_hh[hp] + mbase * 1024,
                           (const char*)g_hl[hp] + mbase * 1024, 1024,
                           (T - 4) * 128);
            }

            // swap prefetched B into current
#pragma unroll
            for (int i = 0; i < 16; i++) Bc[i] = Bn[i];
        }

        // ---- merge chains ----
        float S[16];
#pragma unroll
        for (int a = 0; a < 2; a++)
#pragma unroll
            for (int b = 0; b < 2; b++)
#pragma unroll
                for (int d = 0; d < 4; d++)
                    S[a * 8 + b * 4 + d] =
                        D0[a][b][d] + D1a[a][b][d] + D1b[a][b][d];

        // ---- single-phase cross-kq reduction over the drained 32KB ring ----
        __syncthreads();
        {
            int base = warp * 512 + lane;
#pragma unroll
            for (int f = 0; f < 16; f++) red[base + f * 32] = S[f];
        }
        __syncthreads();
        float a4[4];
#pragma unroll
        for (int g = 0; g < 4; g++)
            a4[g] = (red[bidx[g]] + red[bidx[g] + 2048]) +
                    (red[bidx[g] + 4096] + red[bidx[g] + 6144]);
        __syncthreads();   // reads done before staging overwrites the ring

        // ---- stage next step's x pairs 0,1 (pure x, no h dependency) ----
        if (t + 1 < LL) {
            stage_pair(tid, su, 0, (const char*)g_xh[t + 1] + mbase * 512,
                       (const char*)g_xl[t + 1] + mbase * 512, 512, 0);
            stage_pair(tid, su, 2, (const char*)g_xh[t + 1] + mbase * 512,
                       (const char*)g_xl[t + 1] + mbase * 512, 512, 256);
        }

        // ---- gates + state update + publish ----
        const int pn = (t & 1) ^ 1;
        {
            float iv = sigf(a4[0] + b4[0]);
            float fv = sigf(a4[1] + b4[1]);
            float ov = sigf(a4[2] + b4[2]);
            float gv = tanhf_fast(a4[3] + b4[3]);
            cs = fv * cs + iv * gv;
            float hv = ov * tanhf_fast(cs);
            int mg = mbase + me, hcg = colbase + hce;
            __nv_bfloat16 hi = __float2bfloat16(hv);
            g_hh[pn][mg * HIDDEN + hcg] = hi;
            g_hl[pn][mg * HIDDEN + hcg] = __float2bfloat16(hv - __bfloat162float(hi));
            if (t == LL - 1) out[mg * HIDDEN + hcg] = hv;
        }

        // ---- per-mslice release publish: 1 fence, fan-in 32 (R12-proven) ----
        __syncthreads();
        if (tid == 0) {
            __threadfence();
            unsigned old = atomicAdd(&g_cntM[mslice * 32], 1u);
            if ((old & 31u) == 31u) {
                __threadfence();
                g_genM[mslice * 32] = (unsigned)(t + 1);
            }
        }
    }
}

extern "C" void kernel_launch(void* const* d_in, const int* in_sizes, int n_in,
                              void* d_out, int out_size) {
    const int* X = (const int*)d_in[0];
    const float* E = (const float*)d_in[1];
    const float* Wi = (const float*)d_in[2];
    const float* bi = (const float*)d_in[3];
    const float* Wf = (const float*)d_in[4];
    const float* bf = (const float*)d_in[5];
    const float* Wo = (const float*)d_in[6];
    const float* bo = (const float*)d_in[7];
    const float* Wh = (const float*)d_in[8];
    const float* bh = (const float*)d_in[9];
    float* out = (float*)d_out;

    cudaFuncSetAttribute(lstm_hmma, cudaFuncAttributeMaxDynamicSharedMemorySize,
                         SM_TOT);
    lstm_hmma<<<GCTAS, TTHR, SM_TOT>>>(X, E, Wi, bi, Wf, bf, Wo, bo, Wh, bh, out);
}